// round 3
// baseline (speedup 1.0000x reference)
#include <cuda_runtime.h>
#include <cuda_bf16.h>
#include <math.h>

#define B_  8
#define SQ_ 2048
#define SK_ 2048
#define D_  1024
#define DV_ 1024
#define SCALE (1.0f/32.0f)

#define BM 128
#define BN 128
#define BK 16

// ---------------------------------------------------------------------------
// Kernel 1: raw scores S = (Q @ K^T) * scale into the weights slab.
// 128x128x16 SGEMM tile, 256 threads, 8x8 microtile (4x4 quadrants),
// double-buffered smem. Fully-masked tiles skipped.
// ---------------------------------------------------------------------------
__global__ __launch_bounds__(256) void scores_kernel(
    const float* __restrict__ Q, const float* __restrict__ K,
    const int* __restrict__ qlens, const int* __restrict__ klens,
    float* __restrict__ Sout)
{
    const int b  = blockIdx.z;
    const int q0 = blockIdx.y * BM;
    const int k0 = blockIdx.x * BN;
    const int qlen = qlens[b];
    const int klen = klens[b];
    if (q0 >= qlen || k0 >= klen || k0 > q0 + BM - 1) return;

    __shared__ float As[2][BK][BM];
    __shared__ float Bs[2][BK][BN];

    const int tid = threadIdx.x;
    const int tx = tid & 15;
    const int ty = tid >> 4;

    const int lr = tid >> 1;        // 0..127
    const int lc = (tid & 1) * 8;   // 0 or 8

    const float* Qp = Q + ((size_t)b * SQ_ + q0 + lr) * D_ + lc;
    const float* Kp = K + ((size_t)b * SK_ + k0 + lr) * D_ + lc;

    float4 pa0, pa1, pb0, pb1;
    pa0 = *(const float4*)(Qp);     pa1 = *(const float4*)(Qp + 4);
    pb0 = *(const float4*)(Kp);     pb1 = *(const float4*)(Kp + 4);

#define STORE_TILE(buf)                                                   \
    As[buf][lc+0][lr]=pa0.x; As[buf][lc+1][lr]=pa0.y;                     \
    As[buf][lc+2][lr]=pa0.z; As[buf][lc+3][lr]=pa0.w;                     \
    As[buf][lc+4][lr]=pa1.x; As[buf][lc+5][lr]=pa1.y;                     \
    As[buf][lc+6][lr]=pa1.z; As[buf][lc+7][lr]=pa1.w;                     \
    Bs[buf][lc+0][lr]=pb0.x; Bs[buf][lc+1][lr]=pb0.y;                     \
    Bs[buf][lc+2][lr]=pb0.z; Bs[buf][lc+3][lr]=pb0.w;                     \
    Bs[buf][lc+4][lr]=pb1.x; Bs[buf][lc+5][lr]=pb1.y;                     \
    Bs[buf][lc+6][lr]=pb1.z; Bs[buf][lc+7][lr]=pb1.w;

    STORE_TILE(0)
    __syncthreads();

    float acc[8][8];
#pragma unroll
    for (int i = 0; i < 8; ++i)
#pragma unroll
        for (int j = 0; j < 8; ++j) acc[i][j] = 0.f;

    const int NT = D_ / BK;   // 64
    for (int t = 0; t < NT; ++t) {
        const int buf = t & 1;
        if (t + 1 < NT) {
            const float* q2 = Qp + (t + 1) * BK;
            const float* k2 = Kp + (t + 1) * BK;
            pa0 = *(const float4*)(q2);     pa1 = *(const float4*)(q2 + 4);
            pb0 = *(const float4*)(k2);     pb1 = *(const float4*)(k2 + 4);
        }
#pragma unroll
        for (int p = 0; p < BK; ++p) {
            float4 a0 = *(const float4*)&As[buf][p][ty * 4];
            float4 a1 = *(const float4*)&As[buf][p][ty * 4 + 64];
            float4 b0 = *(const float4*)&Bs[buf][p][tx * 4];
            float4 b1 = *(const float4*)&Bs[buf][p][tx * 4 + 64];
            float ar[8] = {a0.x,a0.y,a0.z,a0.w,a1.x,a1.y,a1.z,a1.w};
            float br[8] = {b0.x,b0.y,b0.z,b0.w,b1.x,b1.y,b1.z,b1.w};
#pragma unroll
            for (int i = 0; i < 8; ++i)
#pragma unroll
                for (int j = 0; j < 8; ++j) acc[i][j] += ar[i] * br[j];
        }
        if (t + 1 < NT) {
            const int nb = buf ^ 1;
            STORE_TILE(nb)
            __syncthreads();
        }
    }

    float* Sp = Sout + ((size_t)b * SQ_ + q0) * SK_ + k0;
#pragma unroll
    for (int hi = 0; hi < 2; ++hi) {
#pragma unroll
        for (int i = 0; i < 4; ++i) {
            const int row = ty * 4 + hi * 64 + i;
            const int ai = hi * 4 + i;
            float4 o0, o1;
            o0.x = acc[ai][0]*SCALE; o0.y = acc[ai][1]*SCALE;
            o0.z = acc[ai][2]*SCALE; o0.w = acc[ai][3]*SCALE;
            o1.x = acc[ai][4]*SCALE; o1.y = acc[ai][5]*SCALE;
            o1.z = acc[ai][6]*SCALE; o1.w = acc[ai][7]*SCALE;
            *(float4*)(Sp + (size_t)row * SK_ + tx * 4)      = o0;
            *(float4*)(Sp + (size_t)row * SK_ + tx * 4 + 64) = o1;
        }
    }
#undef STORE_TILE
}

// ---------------------------------------------------------------------------
// Kernel 2: in-place masked softmax per (b, q) row. Writes exact zeros
// outside the valid prefix; full-zero rows for q >= qlen.
// ---------------------------------------------------------------------------
__global__ __launch_bounds__(256) void softmax_kernel(
    float* __restrict__ Wio,
    const int* __restrict__ qlens, const int* __restrict__ klens)
{
    const int q = blockIdx.x;
    const int b = blockIdx.y;
    const int tid = threadIdx.x;
    float* row = Wio + ((size_t)b * SQ_ + q) * SK_;

    const int qlen = qlens[b];
    const int klen = klens[b];

    if (q >= qlen) {
        float4 z = make_float4(0.f, 0.f, 0.f, 0.f);
        for (int j = tid; j < SK_ / 4; j += 256) ((float4*)row)[j] = z;
        return;
    }

    const int kk = min(klen, q + 1);

    __shared__ float buf[SK_];
    __shared__ float red[256];

    float m = -3.402823466e38f;
    for (int j = tid; j < SK_ / 4; j += 256) {
        float4 s = ((const float4*)row)[j];
        ((float4*)buf)[j] = s;
        int base = j * 4;
        if (base + 0 < kk) m = fmaxf(m, s.x);
        if (base + 1 < kk) m = fmaxf(m, s.y);
        if (base + 2 < kk) m = fmaxf(m, s.z);
        if (base + 3 < kk) m = fmaxf(m, s.w);
    }
    red[tid] = m; __syncthreads();
    for (int off = 128; off > 0; off >>= 1) {
        if (tid < off) red[tid] = fmaxf(red[tid], red[tid + off]);
        __syncthreads();
    }
    m = red[0]; __syncthreads();

    float sum = 0.f;
    for (int j = tid; j < SK_ / 4; j += 256) {
        int base = j * 4;
        float4 s = ((const float4*)buf)[j];
        float4 e;
        e.x = (base + 0 < kk) ? __expf(s.x - m) : 0.f;
        e.y = (base + 1 < kk) ? __expf(s.y - m) : 0.f;
        e.z = (base + 2 < kk) ? __expf(s.z - m) : 0.f;
        e.w = (base + 3 < kk) ? __expf(s.w - m) : 0.f;
        ((float4*)buf)[j] = e;
        sum += e.x + e.y + e.z + e.w;
    }
    red[tid] = sum; __syncthreads();
    for (int off = 128; off > 0; off >>= 1) {
        if (tid < off) red[tid] += red[tid + off];
        __syncthreads();
    }
    const float inv = 1.f / red[0];

    for (int j = tid; j < SK_ / 4; j += 256) {
        float4 e = ((const float4*)buf)[j];
        e.x *= inv; e.y *= inv; e.z *= inv; e.w *= inv;
        ((float4*)row)[j] = e;
    }
}

// ---------------------------------------------------------------------------
// Kernel 3: context = W @ V, same 128x128x16 SGEMM structure. K-loop clamped
// to valid prefix (weights beyond are exact zeros).
// ---------------------------------------------------------------------------
__global__ __launch_bounds__(256) void context_kernel(
    const float* __restrict__ W, const float* __restrict__ V,
    const int* __restrict__ qlens, const int* __restrict__ klens,
    float* __restrict__ C)
{
    const int b  = blockIdx.z;
    const int q0 = blockIdx.y * BM;
    const int v0 = blockIdx.x * BN;
    const int qlen = qlens[b];
    const int klen = klens[b];

    const int tid = threadIdx.x;
    const int tx = tid & 15;
    const int ty = tid >> 4;

    float* Cb = C + ((size_t)b * SQ_ + q0) * DV_ + v0;

    if (q0 >= qlen) {
        float4 z = make_float4(0.f, 0.f, 0.f, 0.f);
#pragma unroll
        for (int hi = 0; hi < 2; ++hi)
#pragma unroll
            for (int i = 0; i < 4; ++i) {
                const int row = ty * 4 + hi * 64 + i;
                *(float4*)(Cb + (size_t)row * DV_ + tx * 4)      = z;
                *(float4*)(Cb + (size_t)row * DV_ + tx * 4 + 64) = z;
            }
        return;
    }

    __shared__ float As[2][BK][BM];
    __shared__ float Bs[2][BK][BN];

    const int lr = tid >> 1;        // 0..127 (W rows)
    const int lc = (tid & 1) * 8;   // 0/8    (W k-cols)
    const int vr = tid >> 4;        // 0..15  (V k-rows)
    const int vc = (tid & 15) * 8;  // V cols

    const float* Wp = W + ((size_t)b * SQ_ + q0 + lr) * SK_ + lc;
    const float* Vp = V + ((size_t)b * SK_ + vr) * DV_ + v0 + vc;

    const int kend  = min(klen, q0 + BM);
    const int NT    = (kend + BK - 1) / BK;   // >= 1

    float4 pa0, pa1, pb0, pb1;
    pa0 = *(const float4*)(Wp);     pa1 = *(const float4*)(Wp + 4);
    pb0 = *(const float4*)(Vp);     pb1 = *(const float4*)(Vp + 4);

#define STORE_TILE_C(buf)                                                 \
    As[buf][lc+0][lr]=pa0.x; As[buf][lc+1][lr]=pa0.y;                     \
    As[buf][lc+2][lr]=pa0.z; As[buf][lc+3][lr]=pa0.w;                     \
    As[buf][lc+4][lr]=pa1.x; As[buf][lc+5][lr]=pa1.y;                     \
    As[buf][lc+6][lr]=pa1.z; As[buf][lc+7][lr]=pa1.w;                     \
    *(float4*)&Bs[buf][vr][vc]     = pb0;                                 \
    *(float4*)&Bs[buf][vr][vc + 4] = pb1;

    STORE_TILE_C(0)
    __syncthreads();

    float acc[8][8];
#pragma unroll
    for (int i = 0; i < 8; ++i)
#pragma unroll
        for (int j = 0; j < 8; ++j) acc[i][j] = 0.f;

    for (int t = 0; t < NT; ++t) {
        const int buf = t & 1;
        if (t + 1 < NT) {
            const float* w2 = Wp + (t + 1) * BK;
            const float* v2 = Vp + (size_t)(t + 1) * BK * DV_;
            pa0 = *(const float4*)(w2);     pa1 = *(const float4*)(w2 + 4);
            pb0 = *(const float4*)(v2);     pb1 = *(const float4*)(v2 + 4);
        }
#pragma unroll
        for (int p = 0; p < BK; ++p) {
            float4 a0 = *(const float4*)&As[buf][p][ty * 4];
            float4 a1 = *(const float4*)&As[buf][p][ty * 4 + 64];
            float4 b0 = *(const float4*)&Bs[buf][p][tx * 4];
            float4 b1 = *(const float4*)&Bs[buf][p][tx * 4 + 64];
            float ar[8] = {a0.x,a0.y,a0.z,a0.w,a1.x,a1.y,a1.z,a1.w};
            float br[8] = {b0.x,b0.y,b0.z,b0.w,b1.x,b1.y,b1.z,b1.w};
#pragma unroll
            for (int i = 0; i < 8; ++i)
#pragma unroll
                for (int j = 0; j < 8; ++j) acc[i][j] += ar[i] * br[j];
        }
        if (t + 1 < NT) {
            const int nb = buf ^ 1;
            STORE_TILE_C(nb)
            __syncthreads();
        }
    }

#pragma unroll
    for (int hi = 0; hi < 2; ++hi) {
#pragma unroll
        for (int i = 0; i < 4; ++i) {
            const int row = ty * 4 + hi * 64 + i;
            const int ai = hi * 4 + i;
            float4 o0, o1;
            o0.x = acc[ai][0]; o0.y = acc[ai][1];
            o0.z = acc[ai][2]; o0.w = acc[ai][3];
            o1.x = acc[ai][4]; o1.y = acc[ai][5];
            o1.z = acc[ai][6]; o1.w = acc[ai][7];
            *(float4*)(Cb + (size_t)row * DV_ + tx * 4)      = o0;
            *(float4*)(Cb + (size_t)row * DV_ + tx * 4 + 64) = o1;
        }
    }
#undef STORE_TILE_C
}

// ---------------------------------------------------------------------------
extern "C" void kernel_launch(void* const* d_in, const int* in_sizes, int n_in,
                              void* d_out, int out_size)
{
    const float* Q = (const float*)d_in[0];
    const float* K = (const float*)d_in[1];
    const float* V = (const float*)d_in[2];
    const int* qlens = (const int*)d_in[3];
    const int* klens = (const int*)d_in[4];

    float* ctx = (float*)d_out;
    float* wts = (float*)d_out + (size_t)B_ * SQ_ * DV_;

    {
        dim3 grid(SK_ / BN, SQ_ / BM, B_);
        scores_kernel<<<grid, 256>>>(Q, K, qlens, klens, wts);
    }
    {
        dim3 grid(SQ_, B_);
        softmax_kernel<<<grid, 256>>>(wts, qlens, klens);
    }
    {
        dim3 grid(DV_ / BN, SQ_ / BM, B_);
        context_kernel<<<grid, 256>>>(wts, V, qlens, klens, ctx);
    }
}

// round 5
// speedup vs baseline: 2.0642x; 2.0642x over previous
#include <cuda_runtime.h>
#include <cuda_bf16.h>
#include <math.h>

#define B_  8
#define SQ_ 2048
#define SK_ 2048
#define D_  1024
#define DV_ 1024
#define SCALE (1.0f/32.0f)

#define BM 128
#define BN 128
#define BK 16
#define KSTRIDE 20   // BK + 4 pad: conflict-free fragment loads

__device__ __forceinline__ unsigned f2tf(float x) {
    unsigned u;
    asm("cvt.rna.tf32.f32 %0, %1;" : "=r"(u) : "f"(x));
    return u;
}

__device__ __forceinline__ void mma_tf32(float c[4], const unsigned a[4], const unsigned b[2]) {
    asm volatile(
        "mma.sync.aligned.m16n8k8.row.col.f32.tf32.tf32.f32 "
        "{%0,%1,%2,%3}, {%4,%5,%6,%7}, {%8,%9}, {%0,%1,%2,%3};"
        : "+f"(c[0]), "+f"(c[1]), "+f"(c[2]), "+f"(c[3])
        : "r"(a[0]), "r"(a[1]), "r"(a[2]), "r"(a[3]), "r"(b[0]), "r"(b[1]));
}

// ---------------------------------------------------------------------------
// Kernel 1: raw scores S = (Q @ K^T) * scale into the weights slab (tf32 MMA).
// 128x128 tile, 8 warps as 4(m) x 2(n), warp tile 32x64 = 2 mfrag x 8 nfrag.
// ---------------------------------------------------------------------------
__global__ __launch_bounds__(256) void scores_kernel(
    const float* __restrict__ Q, const float* __restrict__ K,
    const int* __restrict__ qlens, const int* __restrict__ klens,
    float* __restrict__ Sout)
{
    const int b  = blockIdx.z;
    const int q0 = blockIdx.y * BM;
    const int k0 = blockIdx.x * BN;
    const int qlen = qlens[b];
    const int klen = klens[b];
    if (q0 >= qlen || k0 >= klen || k0 > q0 + BM - 1) return;

    __shared__ unsigned As[2][BM][KSTRIDE];
    __shared__ unsigned Bs[2][BN][KSTRIDE];

    const int tid  = threadIdx.x;
    const int lane = tid & 31;
    const int wid  = tid >> 5;
    const int wm   = (wid >> 1) * 32;   // warp m offset
    const int wn   = (wid & 1) * 64;    // warp n offset
    const int g    = lane >> 2;
    const int t    = lane & 3;

    const int lr = tid >> 1;
    const int lc = (tid & 1) * 8;

    const float* Qp = Q + ((size_t)b * SQ_ + q0 + lr) * D_ + lc;
    const float* Kp = K + ((size_t)b * SK_ + k0 + lr) * D_ + lc;

    float4 pa0 = *(const float4*)(Qp), pa1 = *(const float4*)(Qp + 4);
    float4 pb0 = *(const float4*)(Kp), pb1 = *(const float4*)(Kp + 4);

#define STORE_S(buf)                                                        \
    {                                                                       \
        uint4 ua = make_uint4(f2tf(pa0.x), f2tf(pa0.y), f2tf(pa0.z), f2tf(pa0.w)); \
        uint4 ub = make_uint4(f2tf(pa1.x), f2tf(pa1.y), f2tf(pa1.z), f2tf(pa1.w)); \
        *(uint4*)&As[buf][lr][lc]     = ua;                                 \
        *(uint4*)&As[buf][lr][lc + 4] = ub;                                 \
        uint4 uc = make_uint4(f2tf(pb0.x), f2tf(pb0.y), f2tf(pb0.z), f2tf(pb0.w)); \
        uint4 ud = make_uint4(f2tf(pb1.x), f2tf(pb1.y), f2tf(pb1.z), f2tf(pb1.w)); \
        *(uint4*)&Bs[buf][lr][lc]     = uc;                                 \
        *(uint4*)&Bs[buf][lr][lc + 4] = ud;                                 \
    }

    STORE_S(0)
    __syncthreads();

    float acc[2][8][4];
#pragma unroll
    for (int i = 0; i < 2; ++i)
#pragma unroll
        for (int j = 0; j < 8; ++j)
#pragma unroll
            for (int c = 0; c < 4; ++c) acc[i][j][c] = 0.f;

    const int NT = D_ / BK;   // 64
    for (int it = 0; it < NT; ++it) {
        const int buf = it & 1;
        if (it + 1 < NT) {
            const float* q2 = Qp + (it + 1) * BK;
            const float* k2 = Kp + (it + 1) * BK;
            pa0 = *(const float4*)(q2); pa1 = *(const float4*)(q2 + 4);
            pb0 = *(const float4*)(k2); pb1 = *(const float4*)(k2 + 4);
        }
#pragma unroll
        for (int ks = 0; ks < 2; ++ks) {
            const int kc = ks * 8 + t;
            unsigned a[2][4], bb[8][2];
#pragma unroll
            for (int mf = 0; mf < 2; ++mf) {
                const int row = wm + mf * 16;
                a[mf][0] = As[buf][row + g][kc];
                a[mf][1] = As[buf][row + g + 8][kc];
                a[mf][2] = As[buf][row + g][kc + 4];
                a[mf][3] = As[buf][row + g + 8][kc + 4];
            }
#pragma unroll
            for (int nf = 0; nf < 8; ++nf) {
                const int col = wn + nf * 8;
                bb[nf][0] = Bs[buf][col + g][kc];
                bb[nf][1] = Bs[buf][col + g][kc + 4];
            }
#pragma unroll
            for (int mf = 0; mf < 2; ++mf)
#pragma unroll
                for (int nf = 0; nf < 8; ++nf)
                    mma_tf32(acc[mf][nf], a[mf], bb[nf]);
        }
        if (it + 1 < NT) {
            STORE_S(buf ^ 1)
            __syncthreads();
        }
    }

    float* Sp = Sout + ((size_t)b * SQ_ + q0) * SK_ + k0;
#pragma unroll
    for (int mf = 0; mf < 2; ++mf) {
        const int r0 = wm + mf * 16 + g;
#pragma unroll
        for (int nf = 0; nf < 8; ++nf) {
            const int c0 = wn + nf * 8 + 2 * t;
            float2 v0 = make_float2(acc[mf][nf][0] * SCALE, acc[mf][nf][1] * SCALE);
            float2 v1 = make_float2(acc[mf][nf][2] * SCALE, acc[mf][nf][3] * SCALE);
            *(float2*)(Sp + (size_t)r0 * SK_ + c0)       = v0;
            *(float2*)(Sp + (size_t)(r0 + 8) * SK_ + c0) = v1;
        }
    }
#undef STORE_S
}

// ---------------------------------------------------------------------------
// Kernel 2: in-place masked softmax per row; reads only the valid prefix,
// zero-writes everything else.
// ---------------------------------------------------------------------------
__global__ __launch_bounds__(256) void softmax_kernel(
    float* __restrict__ Wio,
    const int* __restrict__ qlens, const int* __restrict__ klens)
{
    const int q = blockIdx.x;
    const int b = blockIdx.y;
    const int tid = threadIdx.x;
    const int lane = tid & 31;
    const int wid = tid >> 5;
    float* row = Wio + ((size_t)b * SQ_ + q) * SK_;

    const int qlen = qlens[b];
    const int klen = klens[b];

    if (q >= qlen) {
        float4 z = make_float4(0.f, 0.f, 0.f, 0.f);
        for (int j = tid; j < SK_ / 4; j += 256) ((float4*)row)[j] = z;
        return;
    }

    const int kk  = min(klen, q + 1);       // valid prefix length >= 1
    const int kq4 = (kk + 3) >> 2;          // float4s touching valid data

    __shared__ float buf[SK_];
    __shared__ float red[8];

    float m = -3.402823466e38f;
    for (int j = tid; j < kq4; j += 256) {
        float4 s = ((const float4*)row)[j];
        ((float4*)buf)[j] = s;
        int base = j * 4;
        if (base + 0 < kk) m = fmaxf(m, s.x);
        if (base + 1 < kk) m = fmaxf(m, s.y);
        if (base + 2 < kk) m = fmaxf(m, s.z);
        if (base + 3 < kk) m = fmaxf(m, s.w);
    }
#pragma unroll
    for (int o = 16; o > 0; o >>= 1) m = fmaxf(m, __shfl_xor_sync(0xffffffffu, m, o));
    if (lane == 0) red[wid] = m;
    __syncthreads();
    m = red[0];
#pragma unroll
    for (int w = 1; w < 8; ++w) m = fmaxf(m, red[w]);
    __syncthreads();

    float sum = 0.f;
    for (int j = tid; j < kq4; j += 256) {
        int base = j * 4;
        float4 s = ((const float4*)buf)[j];
        float4 e;
        e.x = (base + 0 < kk) ? __expf(s.x - m) : 0.f;
        e.y = (base + 1 < kk) ? __expf(s.y - m) : 0.f;
        e.z = (base + 2 < kk) ? __expf(s.z - m) : 0.f;
        e.w = (base + 3 < kk) ? __expf(s.w - m) : 0.f;
        ((float4*)buf)[j] = e;
        sum += e.x + e.y + e.z + e.w;
    }
#pragma unroll
    for (int o = 16; o > 0; o >>= 1) sum += __shfl_xor_sync(0xffffffffu, sum, o);
    if (lane == 0) red[wid] = sum;
    __syncthreads();
    float tot = red[0];
#pragma unroll
    for (int w = 1; w < 8; ++w) tot += red[w];
    const float inv = 1.f / tot;

    for (int j = tid; j < kq4; j += 256) {
        float4 e = ((const float4*)buf)[j];
        e.x *= inv; e.y *= inv; e.z *= inv; e.w *= inv;
        ((float4*)row)[j] = e;
    }
    float4 z = make_float4(0.f, 0.f, 0.f, 0.f);
    for (int j = kq4 + tid; j < SK_ / 4; j += 256) ((float4*)row)[j] = z;
}

// ---------------------------------------------------------------------------
// Kernel 3: context = W @ V (tf32 MMA), K-loop clamped to the valid prefix.
// Same warp layout as kernel 1. V is transposed into Bs[n][k] at fill time.
// ---------------------------------------------------------------------------
__global__ __launch_bounds__(256) void context_kernel(
    const float* __restrict__ W, const float* __restrict__ V,
    const int* __restrict__ qlens, const int* __restrict__ klens,
    float* __restrict__ C)
{
    const int b  = blockIdx.z;
    const int q0 = blockIdx.y * BM;
    const int v0 = blockIdx.x * BN;
    const int qlen = qlens[b];
    const int klen = klens[b];

    const int tid  = threadIdx.x;
    float* Cb = C + ((size_t)b * SQ_ + q0) * DV_ + v0;

    if (q0 >= qlen) {
        float4 z = make_float4(0.f, 0.f, 0.f, 0.f);
        for (int idx = tid; idx < BM * BN / 4; idx += 256) {
            const int r = idx / (BN / 4);
            const int c = (idx % (BN / 4)) * 4;
            *(float4*)(Cb + (size_t)r * DV_ + c) = z;
        }
        return;
    }

    __shared__ unsigned As[2][BM][KSTRIDE];
    __shared__ unsigned Bs[2][BN][KSTRIDE];

    const int lane = tid & 31;
    const int wid  = tid >> 5;
    const int wm   = (wid >> 1) * 32;
    const int wn   = (wid & 1) * 64;
    const int g    = lane >> 2;
    const int t    = lane & 3;

    const int lr = tid >> 1;
    const int lc = (tid & 1) * 8;
    const int vr = tid >> 4;        // 0..15 : V k-row within slab
    const int vc = tid & 15;        // V col base; cols vc + 16*j

    const float* Wp = W + ((size_t)b * SQ_ + q0 + lr) * SK_ + lc;
    const float* Vp = V + ((size_t)b * SK_ + vr) * DV_ + v0 + vc;

    const int kend = min(klen, q0 + BM);
    const int NT   = (kend + BK - 1) / BK;   // >= 1

    float4 pa0 = *(const float4*)(Wp), pa1 = *(const float4*)(Wp + 4);
    float pv[8];
#pragma unroll
    for (int j = 0; j < 8; ++j) pv[j] = Vp[16 * j];

#define STORE_C(buf)                                                        \
    {                                                                       \
        uint4 ua = make_uint4(f2tf(pa0.x), f2tf(pa0.y), f2tf(pa0.z), f2tf(pa0.w)); \
        uint4 ub = make_uint4(f2tf(pa1.x), f2tf(pa1.y), f2tf(pa1.z), f2tf(pa1.w)); \
        *(uint4*)&As[buf][lr][lc]     = ua;                                 \
        *(uint4*)&As[buf][lr][lc + 4] = ub;                                 \
        _Pragma("unroll")                                                   \
        for (int j = 0; j < 8; ++j) Bs[buf][vc + 16 * j][vr] = f2tf(pv[j]); \
    }

    STORE_C(0)
    __syncthreads();

    float acc[2][8][4];
#pragma unroll
    for (int i = 0; i < 2; ++i)
#pragma unroll
        for (int j = 0; j < 8; ++j)
#pragma unroll
            for (int c = 0; c < 4; ++c) acc[i][j][c] = 0.f;

    for (int it = 0; it < NT; ++it) {
        const int buf = it & 1;
        if (it + 1 < NT) {
            const float* w2 = Wp + (it + 1) * BK;
            const float* v2 = Vp + (size_t)(it + 1) * BK * DV_;
            pa0 = *(const float4*)(w2); pa1 = *(const float4*)(w2 + 4);
#pragma unroll
            for (int j = 0; j < 8; ++j) pv[j] = v2[16 * j];
        }
#pragma unroll
        for (int ks = 0; ks < 2; ++ks) {
            const int kc = ks * 8 + t;
            unsigned a[2][4], bb[8][2];
#pragma unroll
            for (int mf = 0; mf < 2; ++mf) {
                const int row = wm + mf * 16;
                a[mf][0] = As[buf][row + g][kc];
                a[mf][1] = As[buf][row + g + 8][kc];
                a[mf][2] = As[buf][row + g][kc + 4];
                a[mf][3] = As[buf][row + g + 8][kc + 4];
            }
#pragma unroll
            for (int nf = 0; nf < 8; ++nf) {
                const int col = wn + nf * 8;
                bb[nf][0] = Bs[buf][col + g][kc];
                bb[nf][1] = Bs[buf][col + g][kc + 4];
            }
#pragma unroll
            for (int mf = 0; mf < 2; ++mf)
#pragma unroll
                for (int nf = 0; nf < 8; ++nf)
                    mma_tf32(acc[mf][nf], a[mf], bb[nf]);
        }
        if (it + 1 < NT) {
            STORE_C(buf ^ 1)
            __syncthreads();
        }
    }

#pragma unroll
    for (int mf = 0; mf < 2; ++mf) {
        const int r0 = wm + mf * 16 + g;
#pragma unroll
        for (int nf = 0; nf < 8; ++nf) {
            const int c0 = wn + nf * 8 + 2 * t;
            float2 v0r = make_float2(acc[mf][nf][0], acc[mf][nf][1]);
            float2 v1r = make_float2(acc[mf][nf][2], acc[mf][nf][3]);
            *(float2*)(Cb + (size_t)r0 * DV_ + c0)       = v0r;
            *(float2*)(Cb + (size_t)(r0 + 8) * DV_ + c0) = v1r;
        }
    }
#undef STORE_C
}

// ---------------------------------------------------------------------------
extern "C" void kernel_launch(void* const* d_in, const int* in_sizes, int n_in,
                              void* d_out, int out_size)
{
    const float* Q = (const float*)d_in[0];
    const float* K = (const float*)d_in[1];
    const float* V = (const float*)d_in[2];
    const int* qlens = (const int*)d_in[3];
    const int* klens = (const int*)d_in[4];

    float* ctx = (float*)d_out;
    float* wts = (float*)d_out + (size_t)B_ * SQ_ * DV_;

    {
        dim3 grid(SK_ / BN, SQ_ / BM, B_);
        scores_kernel<<<grid, 256>>>(Q, K, qlens, klens, wts);
    }
    {
        dim3 grid(SQ_, B_);
        softmax_kernel<<<grid, 256>>>(wts, qlens, klens);
    }
    {
        dim3 grid(DV_ / BN, SQ_ / BM, B_);
        context_kernel<<<grid, 256>>>(wts, V, qlens, klens, ctx);
    }
}

// round 6
// speedup vs baseline: 2.7683x; 1.3411x over previous
#include <cuda_runtime.h>
#include <cuda_bf16.h>
#include <math.h>

#define B_  8
#define SQ_ 2048
#define SK_ 2048
#define D_  1024
#define DV_ 1024
#define SCALE (1.0f/32.0f)

#define BM 128
#define BN 128
#define BK 16
#define AST 20    // A/W smem row stride (words): conflict-free fragment loads
#define VST 136   // V smem row stride (words): conflict-free b-frag loads

__device__ __forceinline__ unsigned f2tf(float x) {
    unsigned u;
    asm("cvt.rna.tf32.f32 %0, %1;" : "=r"(u) : "f"(x));
    return u;
}

__device__ __forceinline__ void mma_tf32(float c[4], const unsigned a[4], const unsigned b[2]) {
    asm volatile(
        "mma.sync.aligned.m16n8k8.row.col.f32.tf32.tf32.f32 "
        "{%0,%1,%2,%3}, {%4,%5,%6,%7}, {%8,%9}, {%0,%1,%2,%3};"
        : "+f"(c[0]), "+f"(c[1]), "+f"(c[2]), "+f"(c[3])
        : "r"(a[0]), "r"(a[1]), "r"(a[2]), "r"(a[3]), "r"(b[0]), "r"(b[1]));
}

__device__ __forceinline__ void cpa16(void* smem, const void* gmem) {
    unsigned s = (unsigned)__cvta_generic_to_shared(smem);
    asm volatile("cp.async.ca.shared.global [%0], [%1], 16;" :: "r"(s), "l"(gmem));
}
__device__ __forceinline__ void cpa_commit() { asm volatile("cp.async.commit_group;"); }
__device__ __forceinline__ void cpa_wait1()  { asm volatile("cp.async.wait_group 1;"); }
__device__ __forceinline__ void cpa_wait0()  { asm volatile("cp.async.wait_group 0;"); }

// ---------------------------------------------------------------------------
// Kernel 1: raw scores S = (Q @ K^T) * scale (tf32 MMA).
// 128x128 tile, 4 warps as 2x2, warp tile 64x64 = 4 mfrag x 8 nfrag.
// 2-stage cp.async pipeline; fragments loaded fp32 from smem, cvt at consume.
// ---------------------------------------------------------------------------
__global__ __launch_bounds__(128) void scores_kernel(
    const float* __restrict__ Q, const float* __restrict__ K,
    const int* __restrict__ qlens, const int* __restrict__ klens,
    float* __restrict__ Sout)
{
    const int b  = blockIdx.z;
    const int q0 = blockIdx.y * BM;
    const int k0 = blockIdx.x * BN;
    const int qlen = qlens[b];
    const int klen = klens[b];
    if (q0 >= qlen || k0 >= klen || k0 > q0 + BM - 1) return;

    __shared__ float As[2][BM][AST];
    __shared__ float Bs[2][BN][AST];

    const int tid  = threadIdx.x;
    const int lane = tid & 31;
    const int wid  = tid >> 5;          // 0..3
    const int wm   = (wid >> 1) * 64;
    const int wn   = (wid & 1) * 64;
    const int g    = lane >> 2;
    const int t    = lane & 3;

    const float* Qb = Q + ((size_t)b * SQ_ + q0) * D_;
    const float* Kb = K + ((size_t)b * SK_ + k0) * D_;

    // loader: 512 16B-chunks per tile, 4 per thread
    const int lrow0 = tid >> 2;                 // chunk j: row = lrow0 + 32*j
    const int lc4   = (tid & 3) * 4;

#define ISSUE_S(s, it)                                                     \
    {                                                                      \
        const int kofs = (it) * BK;                                        \
        _Pragma("unroll")                                                  \
        for (int j = 0; j < 4; ++j) {                                      \
            const int row = lrow0 + 32 * j;                                \
            cpa16(&As[s][row][lc4], Qb + (size_t)row * D_ + kofs + lc4);   \
            cpa16(&Bs[s][row][lc4], Kb + (size_t)row * D_ + kofs + lc4);   \
        }                                                                  \
        cpa_commit();                                                      \
    }

    const int NT = D_ / BK;   // 64
    ISSUE_S(0, 0)
    ISSUE_S(1, 1)

    float acc[4][8][4];
#pragma unroll
    for (int i = 0; i < 4; ++i)
#pragma unroll
        for (int j = 0; j < 8; ++j)
#pragma unroll
            for (int c = 0; c < 4; ++c) acc[i][j][c] = 0.f;

    for (int it = 0; it < NT; ++it) {
        if (it < NT - 1) cpa_wait1(); else cpa_wait0();
        __syncthreads();
        const int buf = it & 1;
#pragma unroll
        for (int ks = 0; ks < 2; ++ks) {
            const int kc = ks * 8 + t;
            unsigned a[4][4], bb[8][2];
#pragma unroll
            for (int mf = 0; mf < 4; ++mf) {
                const int row = wm + mf * 16;
                a[mf][0] = f2tf(As[buf][row + g][kc]);
                a[mf][1] = f2tf(As[buf][row + g + 8][kc]);
                a[mf][2] = f2tf(As[buf][row + g][kc + 4]);
                a[mf][3] = f2tf(As[buf][row + g + 8][kc + 4]);
            }
#pragma unroll
            for (int nf = 0; nf < 8; ++nf) {
                const int col = wn + nf * 8;
                bb[nf][0] = f2tf(Bs[buf][col + g][kc]);
                bb[nf][1] = f2tf(Bs[buf][col + g][kc + 4]);
            }
#pragma unroll
            for (int mf = 0; mf < 4; ++mf)
#pragma unroll
                for (int nf = 0; nf < 8; ++nf)
                    mma_tf32(acc[mf][nf], a[mf], bb[nf]);
        }
        __syncthreads();
        if (it + 2 < NT) ISSUE_S(buf, it + 2)
    }

    float* Sp = Sout + ((size_t)b * SQ_ + q0) * SK_ + k0;
#pragma unroll
    for (int mf = 0; mf < 4; ++mf) {
        const int r0 = wm + mf * 16 + g;
#pragma unroll
        for (int nf = 0; nf < 8; ++nf) {
            const int c0 = wn + nf * 8 + 2 * t;
            float2 v0 = make_float2(acc[mf][nf][0] * SCALE, acc[mf][nf][1] * SCALE);
            float2 v1 = make_float2(acc[mf][nf][2] * SCALE, acc[mf][nf][3] * SCALE);
            *(float2*)(Sp + (size_t)r0 * SK_ + c0)       = v0;
            *(float2*)(Sp + (size_t)(r0 + 8) * SK_ + c0) = v1;
        }
    }
#undef ISSUE_S
}

// ---------------------------------------------------------------------------
// Kernel 2: in-place masked softmax per row; reads only the valid prefix,
// zero-writes everything else.
// ---------------------------------------------------------------------------
__global__ __launch_bounds__(256) void softmax_kernel(
    float* __restrict__ Wio,
    const int* __restrict__ qlens, const int* __restrict__ klens)
{
    const int q = blockIdx.x;
    const int b = blockIdx.y;
    const int tid = threadIdx.x;
    const int lane = tid & 31;
    const int wid = tid >> 5;
    float* row = Wio + ((size_t)b * SQ_ + q) * SK_;

    const int qlen = qlens[b];
    const int klen = klens[b];

    if (q >= qlen) {
        float4 z = make_float4(0.f, 0.f, 0.f, 0.f);
        for (int j = tid; j < SK_ / 4; j += 256) ((float4*)row)[j] = z;
        return;
    }

    const int kk  = min(klen, q + 1);
    const int kq4 = (kk + 3) >> 2;

    __shared__ float buf[SK_];
    __shared__ float red[8];

    float m = -3.402823466e38f;
    for (int j = tid; j < kq4; j += 256) {
        float4 s = ((const float4*)row)[j];
        ((float4*)buf)[j] = s;
        int base = j * 4;
        if (base + 0 < kk) m = fmaxf(m, s.x);
        if (base + 1 < kk) m = fmaxf(m, s.y);
        if (base + 2 < kk) m = fmaxf(m, s.z);
        if (base + 3 < kk) m = fmaxf(m, s.w);
    }
#pragma unroll
    for (int o = 16; o > 0; o >>= 1) m = fmaxf(m, __shfl_xor_sync(0xffffffffu, m, o));
    if (lane == 0) red[wid] = m;
    __syncthreads();
    m = red[0];
#pragma unroll
    for (int w = 1; w < 8; ++w) m = fmaxf(m, red[w]);
    __syncthreads();

    float sum = 0.f;
    for (int j = tid; j < kq4; j += 256) {
        int base = j * 4;
        float4 s = ((const float4*)buf)[j];
        float4 e;
        e.x = (base + 0 < kk) ? __expf(s.x - m) : 0.f;
        e.y = (base + 1 < kk) ? __expf(s.y - m) : 0.f;
        e.z = (base + 2 < kk) ? __expf(s.z - m) : 0.f;
        e.w = (base + 3 < kk) ? __expf(s.w - m) : 0.f;
        ((float4*)buf)[j] = e;
        sum += e.x + e.y + e.z + e.w;
    }
#pragma unroll
    for (int o = 16; o > 0; o >>= 1) sum += __shfl_xor_sync(0xffffffffu, sum, o);
    if (lane == 0) red[wid] = sum;
    __syncthreads();
    float tot = red[0];
#pragma unroll
    for (int w = 1; w < 8; ++w) tot += red[w];
    const float inv = 1.f / tot;

    for (int j = tid; j < kq4; j += 256) {
        float4 e = ((const float4*)buf)[j];
        e.x *= inv; e.y *= inv; e.z *= inv; e.w *= inv;
        ((float4*)row)[j] = e;
    }
    float4 z = make_float4(0.f, 0.f, 0.f, 0.f);
    for (int j = kq4 + tid; j < SK_ / 4; j += 256) ((float4*)row)[j] = z;
}

// ---------------------------------------------------------------------------
// Kernel 3: context = W @ V (tf32 MMA). Same 64x64 warp tiles + cp.async.
// V kept in k-major smem [k][VST]; K-loop clamped to valid prefix.
// ---------------------------------------------------------------------------
__global__ __launch_bounds__(128) void context_kernel(
    const float* __restrict__ W, const float* __restrict__ V,
    const int* __restrict__ qlens, const int* __restrict__ klens,
    float* __restrict__ C)
{
    const int b  = blockIdx.z;
    const int q0 = blockIdx.y * BM;
    const int v0 = blockIdx.x * BN;
    const int qlen = qlens[b];
    const int klen = klens[b];

    const int tid  = threadIdx.x;
    float* Cb = C + ((size_t)b * SQ_ + q0) * DV_ + v0;

    if (q0 >= qlen) {
        float4 z = make_float4(0.f, 0.f, 0.f, 0.f);
        for (int idx = tid; idx < BM * BN / 4; idx += 128) {
            const int r = idx / (BN / 4);
            const int c = (idx % (BN / 4)) * 4;
            *(float4*)(Cb + (size_t)r * DV_ + c) = z;
        }
        return;
    }

    __shared__ float Ws[2][BM][AST];
    __shared__ float Vs[2][BK][VST];

    const int lane = tid & 31;
    const int wid  = tid >> 5;
    const int wm   = (wid >> 1) * 64;
    const int wn   = (wid & 1) * 64;
    const int g    = lane >> 2;
    const int t    = lane & 3;

    const float* Wb = W + ((size_t)b * SQ_ + q0) * SK_;
    const float* Vb = V + (size_t)b * SK_ * DV_ + v0;

    const int lrow0 = tid >> 2;             // W loader: rows lrow0+32j
    const int lc4   = (tid & 3) * 4;
    const int vk0   = tid >> 5;             // V loader: k rows vk0+4j
    const int vn4   = (tid & 31) * 4;

#define ISSUE_C(s, it)                                                       \
    {                                                                        \
        const int kofs = (it) * BK;                                          \
        _Pragma("unroll")                                                    \
        for (int j = 0; j < 4; ++j) {                                        \
            const int row = lrow0 + 32 * j;                                  \
            cpa16(&Ws[s][row][lc4], Wb + (size_t)row * SK_ + kofs + lc4);    \
        }                                                                    \
        _Pragma("unroll")                                                    \
        for (int j = 0; j < 4; ++j) {                                        \
            const int kr = vk0 + 4 * j;                                      \
            cpa16(&Vs[s][kr][vn4], Vb + (size_t)(kofs + kr) * DV_ + vn4);    \
        }                                                                    \
        cpa_commit();                                                        \
    }

    const int kend = min(klen, q0 + BM);
    const int NT   = (kend + BK - 1) / BK;   // >= 1

    ISSUE_C(0, 0)
    if (NT > 1) ISSUE_C(1, 1)

    float acc[4][8][4];
#pragma unroll
    for (int i = 0; i < 4; ++i)
#pragma unroll
        for (int j = 0; j < 8; ++j)
#pragma unroll
            for (int c = 0; c < 4; ++c) acc[i][j][c] = 0.f;

    for (int it = 0; it < NT; ++it) {
        if (it < NT - 1) cpa_wait1(); else cpa_wait0();
        __syncthreads();
        const int buf = it & 1;
#pragma unroll
        for (int ks = 0; ks < 2; ++ks) {
            const int kc = ks * 8 + t;
            unsigned a[4][4], bb[8][2];
#pragma unroll
            for (int mf = 0; mf < 4; ++mf) {
                const int row = wm + mf * 16;
                a[mf][0] = f2tf(Ws[buf][row + g][kc]);
                a[mf][1] = f2tf(Ws[buf][row + g + 8][kc]);
                a[mf][2] = f2tf(Ws[buf][row + g][kc + 4]);
                a[mf][3] = f2tf(Ws[buf][row + g + 8][kc + 4]);
            }
#pragma unroll
            for (int nf = 0; nf < 8; ++nf) {
                const int col = wn + nf * 8;
                bb[nf][0] = f2tf(Vs[buf][kc][col + g]);
                bb[nf][1] = f2tf(Vs[buf][kc + 4][col + g]);
            }
#pragma unroll
            for (int mf = 0; mf < 4; ++mf)
#pragma unroll
                for (int nf = 0; nf < 8; ++nf)
                    mma_tf32(acc[mf][nf], a[mf], bb[nf]);
        }
        __syncthreads();
        if (it + 2 < NT) ISSUE_C(buf, it + 2)
    }

#pragma unroll
    for (int mf = 0; mf < 4; ++mf) {
        const int r0 = wm + mf * 16 + g;
#pragma unroll
        for (int nf = 0; nf < 8; ++nf) {
            const int c0 = wn + nf * 8 + 2 * t;
            float2 v0r = make_float2(acc[mf][nf][0], acc[mf][nf][1]);
            float2 v1r = make_float2(acc[mf][nf][2], acc[mf][nf][3]);
            *(float2*)(Cb + (size_t)r0 * DV_ + c0)       = v0r;
            *(float2*)(Cb + (size_t)(r0 + 8) * DV_ + c0) = v1r;
        }
    }
#undef ISSUE_C
}

// ---------------------------------------------------------------------------
extern "C" void kernel_launch(void* const* d_in, const int* in_sizes, int n_in,
                              void* d_out, int out_size)
{
    const float* Q = (const float*)d_in[0];
    const float* K = (const float*)d_in[1];
    const float* V = (const float*)d_in[2];
    const int* qlens = (const int*)d_in[3];
    const int* klens = (const int*)d_in[4];

    float* ctx = (float*)d_out;
    float* wts = (float*)d_out + (size_t)B_ * SQ_ * DV_;

    {
        dim3 grid(SK_ / BN, SQ_ / BM, B_);
        scores_kernel<<<grid, 128>>>(Q, K, qlens, klens, wts);
    }
    {
        dim3 grid(SQ_, B_);
        softmax_kernel<<<grid, 256>>>(wts, qlens, klens);
    }
    {
        dim3 grid(DV_ / BN, SQ_ / BM, B_);
        context_kernel<<<grid, 128>>>(wts, V, qlens, klens, ctx);
    }
}